// round 15
// baseline (speedup 1.0000x reference)
#include <cuda_runtime.h>
#include <cuda_fp16.h>
#include <cstdint>

#define T_SEQ   4096
#define D_EMBD  1024
#define N_HEADS 16
#define D_HEAD  64

// fp16 scratch (device globals — no runtime allocation allowed)
__device__ __half g_xh[(size_t)T_SEQ * D_EMBD];
__device__ __half g_w1h[(size_t)D_EMBD * 3 * D_EMBD];
__device__ __half g_w2h[(size_t)D_EMBD * D_EMBD];
__device__ __half g_kqv[(size_t)T_SEQ * 3 * D_EMBD];
__device__ __half g_att[(size_t)T_SEQ * D_EMBD];

// ---------------------------------------------------------------------------
// Helpers
// ---------------------------------------------------------------------------
__device__ __forceinline__ uint32_t smem_u32(const void* p) {
    uint32_t a;
    asm("{ .reg .u64 t; cvta.to.shared.u64 t, %1; cvt.u32.u64 %0, t; }"
        : "=r"(a) : "l"(p));
    return a;
}
__device__ __forceinline__ void ldsm4(uint32_t* r, uint32_t addr) {
    asm volatile("ldmatrix.sync.aligned.m8n8.x4.shared.b16 {%0,%1,%2,%3}, [%4];"
                 : "=r"(r[0]), "=r"(r[1]), "=r"(r[2]), "=r"(r[3]) : "r"(addr));
}
__device__ __forceinline__ void ldsm4t(uint32_t* r, uint32_t addr) {
    asm volatile("ldmatrix.sync.aligned.m8n8.x4.trans.shared.b16 {%0,%1,%2,%3}, [%4];"
                 : "=r"(r[0]), "=r"(r[1]), "=r"(r[2]), "=r"(r[3]) : "r"(addr));
}
__device__ __forceinline__ void mma_f16(float* c, const uint32_t* a,
                                        uint32_t b0, uint32_t b1) {
    asm volatile(
        "mma.sync.aligned.m16n8k16.row.col.f32.f16.f16.f32 "
        "{%0,%1,%2,%3}, {%4,%5,%6,%7}, {%8,%9}, {%0,%1,%2,%3};"
        : "+f"(c[0]), "+f"(c[1]), "+f"(c[2]), "+f"(c[3])
        : "r"(a[0]), "r"(a[1]), "r"(a[2]), "r"(a[3]), "r"(b0), "r"(b1));
}
__device__ __forceinline__ void cpa16(uint32_t dst, const void* src) {
    asm volatile("cp.async.cg.shared.global [%0], [%1], 16;" :: "r"(dst), "l"(src));
}
#define CP_COMMIT() asm volatile("cp.async.commit_group;" ::: "memory")
#define CP_WAIT(n)  asm volatile("cp.async.wait_group %0;" :: "n"(n) : "memory")

__device__ __forceinline__ uint32_t pack2h(float v0, float v1) {
    __half2 p = __floats2half2_rn(v0, v1);
    return *(uint32_t*)&p;
}

// ---------------------------------------------------------------------------
// Fused prepass: fp32 -> fp16 for x, W1, W2 in ONE launch (grid-stride)
// ---------------------------------------------------------------------------
__global__ void conv_all(const float* __restrict__ x,  __half* __restrict__ xh,  int nx,
                         const float* __restrict__ w1, __half* __restrict__ w1h, int nw1,
                         const float* __restrict__ w2, __half* __restrict__ w2h, int nw2)
{
    int total = (nx + nw1 + nw2) >> 2;
    for (int t = blockIdx.x * blockDim.x + threadIdx.x; t < total;
         t += gridDim.x * blockDim.x) {
        int idx = t * 4;
        const float* src;
        __half* dst;
        if (idx < nx)            { src = x + idx;               dst = xh + idx; }
        else if (idx < nx + nw1) { src = w1 + (idx - nx);       dst = w1h + (idx - nx); }
        else                     { src = w2 + (idx - nx - nw1); dst = w2h + (idx - nx - nw1); }
        float4 v = *(const float4*)src;
        *(uint2*)dst = make_uint2(pack2h(v.x, v.y), pack2h(v.z, v.w));
    }
}

// ---------------------------------------------------------------------------
// Pipelined fp16 GEMM: C = A@B (+bias). BM=BN=128, BK=64, 3-stage, 2 CTAs/SM.
// ---------------------------------------------------------------------------
#define SA_H  0
#define SB_H  16384
#define STAGE_SZ 32768
#define G_SMEM (STAGE_SZ * 3)

__global__ __launch_bounds__(256, 2)
void gemm_tc(const __half* __restrict__ Ah, const __half* __restrict__ Bh,
             const float* __restrict__ bias,
             float* __restrict__ Cf, __half* __restrict__ Hout,
             int M, int N, int K)
{
    extern __shared__ char sm[];
    const uint32_t smb = smem_u32(sm);
    const int tid = threadIdx.x;
    const int w = tid >> 5, lane = tid & 31;
    const int wm = w >> 2, wn = w & 3;
    const int row0 = blockIdx.y * 128, col0 = blockIdx.x * 128;

    float acc[4][4][4];
    #pragma unroll
    for (int a = 0; a < 4; a++)
        #pragma unroll
        for (int b = 0; b < 4; b++)
            #pragma unroll
            for (int cc = 0; cc < 4; cc++) acc[a][b][cc] = 0.0f;

    const int nchunk = K >> 6;

    #define G_ISSUE(kc)                                                         \
    do {                                                                        \
        uint32_t base = smb + ((kc) % 3) * STAGE_SZ;                            \
        _Pragma("unroll")                                                       \
        for (int l = 0; l < 4; l++) {                                           \
            int slot = tid + l * 256;                                           \
            int ar = slot >> 3, aq = slot & 7;                                  \
            uint32_t aoff = (uint32_t)(ar * 128 + ((aq ^ (ar & 7)) << 4));      \
            size_t ga = (size_t)(row0 + ar) * K + (kc) * 64 + aq * 8;           \
            cpa16(base + SA_H + aoff, Ah + ga);                                 \
            int br = slot >> 4, bq = slot & 15;                                 \
            uint32_t boff = (uint32_t)(br * 256 + ((bq ^ (br & 7)) << 4));      \
            size_t gb = (size_t)((kc) * 64 + br) * N + col0 + bq * 8;           \
            cpa16(base + SB_H + boff, Bh + gb);                                 \
        }                                                                       \
    } while (0)

    G_ISSUE(0); CP_COMMIT();
    G_ISSUE(1); CP_COMMIT();

    for (int kc = 0; kc < nchunk; kc++) {
        if (kc == nchunk - 1) { CP_WAIT(0); } else { CP_WAIT(1); }
        __syncthreads();
        if (kc + 2 < nchunk) G_ISSUE(kc + 2);
        CP_COMMIT();

        const uint32_t sbase = smb + (kc % 3) * STAGE_SZ;
        const int arow = wm * 64 + (lane & 15);
        #pragma unroll
        for (int ks = 0; ks < 4; ks++) {
            uint32_t ah[4][4], bh[2][4];
            const int aq = ks * 2 + (lane >> 4);
            const uint32_t aswz = (uint32_t)((aq ^ (lane & 7)) << 4);
            #pragma unroll
            for (int tm = 0; tm < 4; tm++) {
                uint32_t ad = sbase + SA_H + (uint32_t)((arow + tm * 16) * 128) + aswz;
                ldsm4(ah[tm], ad);
            }
            const int brow = ks * 16 + (lane & 7) + (lane & 8);
            #pragma unroll
            for (int t2 = 0; t2 < 2; t2++) {
                int bq = wn * 4 + (lane >> 4) + t2 * 2;
                uint32_t bd = sbase + SB_H +
                              (uint32_t)(brow * 256 + ((bq ^ (lane & 7)) << 4));
                ldsm4t(bh[t2], bd);
            }
            #pragma unroll
            for (int tm = 0; tm < 4; tm++)
                #pragma unroll
                for (int tn = 0; tn < 4; tn++)
                    mma_f16(acc[tm][tn], ah[tm],
                            bh[tn >> 1][(tn & 1) * 2], bh[tn >> 1][(tn & 1) * 2 + 1]);
        }
    }

    #pragma unroll
    for (int tm = 0; tm < 4; tm++) {
        int r = row0 + wm * 64 + tm * 16 + (lane >> 2);
        #pragma unroll
        for (int tn = 0; tn < 4; tn++) {
            int c = col0 + wn * 32 + tn * 8 + 2 * (lane & 3);
            float2 bv = *(const float2*)(bias + c);
            float c0 = acc[tm][tn][0] + bv.x, c1 = acc[tm][tn][1] + bv.y;
            float c2 = acc[tm][tn][2] + bv.x, c3 = acc[tm][tn][3] + bv.y;
            if (Cf) {
                *(float2*)(Cf + (size_t)r * N + c) = make_float2(c0, c1);
                *(float2*)(Cf + (size_t)(r + 8) * N + c) = make_float2(c2, c3);
            } else {
                *(uint32_t*)(Hout + (size_t)r * N + c) = pack2h(c0, c1);
                *(uint32_t*)(Hout + (size_t)(r + 8) * N + c) = pack2h(c2, c3);
            }
        }
    }
}

// ---------------------------------------------------------------------------
// Attention, pure fp16, 2 CTAs/SM: 8 warps x 16 rows, each warp covers all
// 128 keys of a block in two sequential 64-key halves (sacc only 32 regs
// live). No cross-warp reduction. 2 KV buffers, depth-1 prefetch.
// ---------------------------------------------------------------------------
#define AQ_H 0
#define AKV(buf) (16384 + (buf) * 32768)   // per buf: K 16K, V 16K
#define A_SMEM 81920

__global__ __launch_bounds__(256, 2)
void attn_tc(const __half* __restrict__ kqv, __half* __restrict__ att)
{
    extern __shared__ char sm[];
    const uint32_t smb = smem_u32(sm);
    const int tid = threadIdx.x;
    const int w = tid >> 5, lane = tid & 31;   // warp = 16-row group
    const int i = 31 - blockIdx.x;             // heavy tiles first
    const int h = blockIdx.y;
    const int row0 = i * 128;
    const int ldg = 3 * D_EMBD;

    const __half* qg = kqv + D_EMBD + h * D_HEAD;     // split order: k, q, v
    const __half* kg = kqv + h * D_HEAD;
    const __half* vg = kqv + 2 * D_EMBD + h * D_HEAD;

    #define KV_ISSUE(jblk, buf)                                                 \
    do {                                                                        \
        uint32_t kb = smb + AKV(buf);                                           \
        _Pragma("unroll")                                                       \
        for (int l = 0; l < 4; l++) {                                           \
            int slot = tid + l * 256;                                           \
            int r = slot >> 3, q = slot & 7;                                    \
            uint32_t d = (uint32_t)(r * 128 + ((q ^ (r & 7)) << 4));            \
            size_t go = (size_t)((jblk) * 128 + r) * ldg + q * 8;               \
            cpa16(kb + d, kg + go);                                             \
            cpa16(kb + 16384 + d, vg + go);                                     \
        }                                                                       \
    } while (0)

    // issue Q tile + KV block 0, wait for both
    #pragma unroll
    for (int l = 0; l < 2; l++) {
        int slot = tid + l * 256;
        int r = slot >> 2, q2 = (slot & 3) * 2;     // 2 chunks of 16B per row
        uint32_t d = (uint32_t)(r * 128 + ((q2 ^ (r & 7)) << 4));
        uint32_t d2 = (uint32_t)(r * 128 + (((q2 + 1) ^ (r & 7)) << 4));
        size_t go = (size_t)(row0 + r) * ldg + q2 * 8;
        cpa16(smb + AQ_H + d, qg + go);
        cpa16(smb + AQ_H + d2, qg + go + 8);
    }
    KV_ISSUE(0, 0);
    CP_COMMIT();
    CP_WAIT(0);
    __syncthreads();

    // ---- hoist Q fragments (16 rows x 64 k) into registers ----
    uint32_t qf[4][4];
    #pragma unroll
    for (int ks = 0; ks < 4; ks++) {
        const int aq = ks * 2 + (lane >> 4);
        const uint32_t aswz = (uint32_t)((aq ^ (lane & 7)) << 4);
        uint32_t ad = smb + AQ_H +
                      (uint32_t)((w * 16 + (lane & 15)) * 128) + aswz;
        ldsm4(qf[ks], ad);
    }

    float oacc[8][4];
    #pragma unroll
    for (int b = 0; b < 8; b++)
        #pragma unroll
        for (int cc = 0; cc < 4; cc++) oacc[b][cc] = 0.0f;

    for (int j = 0; j <= i; j++) {
        if (j > 0) {
            CP_WAIT(0);
            __syncthreads();
        }
        if (j + 1 <= i) { KV_ISSUE(j + 1, (j + 1) & 1); CP_COMMIT(); }

        const uint32_t kvb = smb + AKV(j & 1);

        #pragma unroll
        for (int h2 = 0; h2 < 2; h2++) {           // 64-key halves, sequential
            // ---- S(16 x 64) = Q @ K^T ----
            float sacc[8][4];
            #pragma unroll
            for (int b = 0; b < 8; b++)
                #pragma unroll
                for (int cc = 0; cc < 4; cc++) sacc[b][cc] = 0.0f;

            #pragma unroll
            for (int ks = 0; ks < 4; ks++) {
                uint32_t kb[4][4];
                const int kq = ks * 2 + ((lane >> 3) & 1);
                const uint32_t kswz = (uint32_t)((kq ^ (lane & 7)) << 4);
                #pragma unroll
                for (int g = 0; g < 4; g++) {
                    int krow = h2 * 64 + g * 16 + (lane & 7) + ((lane >> 1) & 8);
                    ldsm4(kb[g], kvb + (uint32_t)(krow * 128) + kswz);
                }
                #pragma unroll
                for (int nt = 0; nt < 8; nt++)
                    mma_f16(sacc[nt], qf[ks],
                            kb[nt >> 1][(nt & 1) * 2], kb[nt >> 1][(nt & 1) * 2 + 1]);
            }

            // ---- causal mask (diag block only), in registers ----
            if (j == i) {
                int rl = w * 16 + (lane >> 2);
                #pragma unroll
                for (int nt = 0; nt < 8; nt++) {
                    int cl = h2 * 64 + nt * 8 + 2 * (lane & 3);
                    if (cl     > rl)     sacc[nt][0] = 0.0f;
                    if (cl + 1 > rl)     sacc[nt][1] = 0.0f;
                    if (cl     > rl + 8) sacc[nt][2] = 0.0f;
                    if (cl + 1 > rl + 8) sacc[nt][3] = 0.0f;
                }
            }

            // ---- O += S @ V ----
            #pragma unroll
            for (int ksl = 0; ksl < 4; ksl++) {
                uint32_t sa[4], vb[4][4];
                sa[0] = pack2h(sacc[2 * ksl][0],     sacc[2 * ksl][1]);
                sa[1] = pack2h(sacc[2 * ksl][2],     sacc[2 * ksl][3]);
                sa[2] = pack2h(sacc[2 * ksl + 1][0], sacc[2 * ksl + 1][1]);
                sa[3] = pack2h(sacc[2 * ksl + 1][2], sacc[2 * ksl + 1][3]);
                const int vrow = h2 * 64 + ksl * 16 + (lane & 7) + (lane & 8);
                #pragma unroll
                for (int g2 = 0; g2 < 4; g2++) {
                    int vq = g2 * 2 + (lane >> 4);
                    ldsm4t(vb[g2], kvb + 16384 +
                           (uint32_t)(vrow * 128 + ((vq ^ (lane & 7)) << 4)));
                }
                #pragma unroll
                for (int nt = 0; nt < 8; nt++)
                    mma_f16(oacc[nt], sa,
                            vb[nt >> 1][(nt & 1) * 2], vb[nt >> 1][(nt & 1) * 2 + 1]);
            }
        }
    }

    // ---- epilogue: each warp owns its 16 rows fully ----
    {
        int r = row0 + w * 16 + (lane >> 2);
        #pragma unroll
        for (int nt = 0; nt < 8; nt++) {
            int c = h * D_HEAD + nt * 8 + 2 * (lane & 3);
            *(uint32_t*)(att + (size_t)r * D_EMBD + c) =
                pack2h(oacc[nt][0], oacc[nt][1]);
            *(uint32_t*)(att + (size_t)(r + 8) * D_EMBD + c) =
                pack2h(oacc[nt][2], oacc[nt][3]);
        }
    }
}

// ---------------------------------------------------------------------------
extern "C" void kernel_launch(void* const* d_in, const int* in_sizes, int n_in,
                              void* d_out, int out_size)
{
    const float* x  = (const float*)d_in[0];
    const float* W1 = (const float*)d_in[1];
    const float* b1 = (const float*)d_in[2];
    const float* W2 = (const float*)d_in[3];
    const float* b2 = (const float*)d_in[4];
    float* out = (float*)d_out;

    __half *xh, *w1h, *w2h, *kqv, *att;
    cudaGetSymbolAddress((void**)&xh, g_xh);
    cudaGetSymbolAddress((void**)&w1h, g_w1h);
    cudaGetSymbolAddress((void**)&w2h, g_w2h);
    cudaGetSymbolAddress((void**)&kqv, g_kqv);
    cudaGetSymbolAddress((void**)&att, g_att);

    cudaFuncSetAttribute(gemm_tc, cudaFuncAttributeMaxDynamicSharedMemorySize, G_SMEM);
    cudaFuncSetAttribute(attn_tc, cudaFuncAttributeMaxDynamicSharedMemorySize, A_SMEM);

    int nx = T_SEQ * D_EMBD, nw1 = D_EMBD * 3 * D_EMBD, nw2 = D_EMBD * D_EMBD;
    conv_all<<<1184, 256>>>(x, xh, nx, W1, w1h, nw1, W2, w2h, nw2);

    // kqv = x @ W1 + b1   (fp16 output)
    gemm_tc<<<dim3(3 * D_EMBD / 128, T_SEQ / 128), 256, G_SMEM>>>(
        xh, w1h, b1, nullptr, kqv, T_SEQ, 3 * D_EMBD, D_EMBD);

    attn_tc<<<dim3(T_SEQ / 128, N_HEADS), 256, A_SMEM>>>(kqv, att);

    // out = att @ W2 + b2  (fp32 output)
    gemm_tc<<<dim3(D_EMBD / 128, T_SEQ / 128), 256, G_SMEM>>>(
        att, w2h, b2, out, nullptr, T_SEQ, D_EMBD, D_EMBD);
}

// round 16
// speedup vs baseline: 1.0141x; 1.0141x over previous
#include <cuda_runtime.h>
#include <cuda_fp16.h>
#include <cstdint>

#define T_SEQ   4096
#define D_EMBD  1024
#define N_HEADS 16
#define D_HEAD  64

// fp16 scratch (device globals — no runtime allocation allowed)
__device__ __half g_xh[(size_t)T_SEQ * D_EMBD];
__device__ __half g_w1h[(size_t)D_EMBD * 3 * D_EMBD];
__device__ __half g_w2h[(size_t)D_EMBD * D_EMBD];
__device__ __half g_kqv[(size_t)T_SEQ * 3 * D_EMBD];
__device__ __half g_att[(size_t)T_SEQ * D_EMBD];

// ---------------------------------------------------------------------------
// Helpers
// ---------------------------------------------------------------------------
__device__ __forceinline__ uint32_t smem_u32(const void* p) {
    uint32_t a;
    asm("{ .reg .u64 t; cvta.to.shared.u64 t, %1; cvt.u32.u64 %0, t; }"
        : "=r"(a) : "l"(p));
    return a;
}
__device__ __forceinline__ void ldsm4(uint32_t* r, uint32_t addr) {
    asm volatile("ldmatrix.sync.aligned.m8n8.x4.shared.b16 {%0,%1,%2,%3}, [%4];"
                 : "=r"(r[0]), "=r"(r[1]), "=r"(r[2]), "=r"(r[3]) : "r"(addr));
}
__device__ __forceinline__ void ldsm4t(uint32_t* r, uint32_t addr) {
    asm volatile("ldmatrix.sync.aligned.m8n8.x4.trans.shared.b16 {%0,%1,%2,%3}, [%4];"
                 : "=r"(r[0]), "=r"(r[1]), "=r"(r[2]), "=r"(r[3]) : "r"(addr));
}
__device__ __forceinline__ void mma_f16(float* c, const uint32_t* a,
                                        uint32_t b0, uint32_t b1) {
    asm volatile(
        "mma.sync.aligned.m16n8k16.row.col.f32.f16.f16.f32 "
        "{%0,%1,%2,%3}, {%4,%5,%6,%7}, {%8,%9}, {%0,%1,%2,%3};"
        : "+f"(c[0]), "+f"(c[1]), "+f"(c[2]), "+f"(c[3])
        : "r"(a[0]), "r"(a[1]), "r"(a[2]), "r"(a[3]), "r"(b0), "r"(b1));
}
__device__ __forceinline__ void cpa16(uint32_t dst, const void* src) {
    asm volatile("cp.async.cg.shared.global [%0], [%1], 16;" :: "r"(dst), "l"(src));
}
#define CP_COMMIT() asm volatile("cp.async.commit_group;" ::: "memory")
#define CP_WAIT(n)  asm volatile("cp.async.wait_group %0;" :: "n"(n) : "memory")

__device__ __forceinline__ uint32_t pack2h(float v0, float v1) {
    __half2 p = __floats2half2_rn(v0, v1);
    return *(uint32_t*)&p;
}

// ---------------------------------------------------------------------------
// Prepass: fp32 -> fp16, one-shot, 4 independent float4s per thread (MLP=4).
// Laid out over the concatenation x | W1 | W2 (all multiples of 16 elems).
// ---------------------------------------------------------------------------
__global__ void conv_all(const float* __restrict__ x,  __half* __restrict__ xh,  int nx,
                         const float* __restrict__ w1, __half* __restrict__ w1h, int nw1,
                         const float* __restrict__ w2, __half* __restrict__ w2h, int nw2)
{
    int base = (blockIdx.x * blockDim.x + threadIdx.x) * 16;   // 16 floats
    int total = nx + nw1 + nw2;
    if (base >= total) return;
    const float* src;
    __half* dst;
    if (base < nx)            { src = x + base;               dst = xh + base; }
    else if (base < nx + nw1) { src = w1 + (base - nx);       dst = w1h + (base - nx); }
    else                      { src = w2 + (base - nx - nw1); dst = w2h + (base - nx - nw1); }
    float4 v0 = *(const float4*)(src + 0);
    float4 v1 = *(const float4*)(src + 4);
    float4 v2 = *(const float4*)(src + 8);
    float4 v3 = *(const float4*)(src + 12);
    *(uint2*)(dst + 0)  = make_uint2(pack2h(v0.x, v0.y), pack2h(v0.z, v0.w));
    *(uint2*)(dst + 4)  = make_uint2(pack2h(v1.x, v1.y), pack2h(v1.z, v1.w));
    *(uint2*)(dst + 8)  = make_uint2(pack2h(v2.x, v2.y), pack2h(v2.z, v2.w));
    *(uint2*)(dst + 12) = make_uint2(pack2h(v3.x, v3.y), pack2h(v3.z, v3.w));
}

// ---------------------------------------------------------------------------
// Pipelined fp16 GEMM: C = A@B (+bias). BM=BN=128, BK=64, 3-stage, 2 CTAs/SM.
// ---------------------------------------------------------------------------
#define SA_H  0
#define SB_H  16384
#define STAGE_SZ 32768
#define G_SMEM (STAGE_SZ * 3)

__global__ __launch_bounds__(256, 2)
void gemm_tc(const __half* __restrict__ Ah, const __half* __restrict__ Bh,
             const float* __restrict__ bias,
             float* __restrict__ Cf, __half* __restrict__ Hout,
             int M, int N, int K)
{
    extern __shared__ char sm[];
    const uint32_t smb = smem_u32(sm);
    const int tid = threadIdx.x;
    const int w = tid >> 5, lane = tid & 31;
    const int wm = w >> 2, wn = w & 3;
    const int row0 = blockIdx.y * 128, col0 = blockIdx.x * 128;

    float acc[4][4][4];
    #pragma unroll
    for (int a = 0; a < 4; a++)
        #pragma unroll
        for (int b = 0; b < 4; b++)
            #pragma unroll
            for (int cc = 0; cc < 4; cc++) acc[a][b][cc] = 0.0f;

    const int nchunk = K >> 6;

    #define G_ISSUE(kc)                                                         \
    do {                                                                        \
        uint32_t base = smb + ((kc) % 3) * STAGE_SZ;                            \
        _Pragma("unroll")                                                       \
        for (int l = 0; l < 4; l++) {                                           \
            int slot = tid + l * 256;                                           \
            int ar = slot >> 3, aq = slot & 7;                                  \
            uint32_t aoff = (uint32_t)(ar * 128 + ((aq ^ (ar & 7)) << 4));      \
            size_t ga = (size_t)(row0 + ar) * K + (kc) * 64 + aq * 8;           \
            cpa16(base + SA_H + aoff, Ah + ga);                                 \
            int br = slot >> 4, bq = slot & 15;                                 \
            uint32_t boff = (uint32_t)(br * 256 + ((bq ^ (br & 7)) << 4));      \
            size_t gb = (size_t)((kc) * 64 + br) * N + col0 + bq * 8;           \
            cpa16(base + SB_H + boff, Bh + gb);                                 \
        }                                                                       \
    } while (0)

    G_ISSUE(0); CP_COMMIT();
    G_ISSUE(1); CP_COMMIT();

    for (int kc = 0; kc < nchunk; kc++) {
        if (kc == nchunk - 1) { CP_WAIT(0); } else { CP_WAIT(1); }
        __syncthreads();
        if (kc + 2 < nchunk) G_ISSUE(kc + 2);
        CP_COMMIT();

        const uint32_t sbase = smb + (kc % 3) * STAGE_SZ;
        const int arow = wm * 64 + (lane & 15);
        #pragma unroll
        for (int ks = 0; ks < 4; ks++) {
            uint32_t ah[4][4], bh[2][4];
            const int aq = ks * 2 + (lane >> 4);
            const uint32_t aswz = (uint32_t)((aq ^ (lane & 7)) << 4);
            #pragma unroll
            for (int tm = 0; tm < 4; tm++) {
                uint32_t ad = sbase + SA_H + (uint32_t)((arow + tm * 16) * 128) + aswz;
                ldsm4(ah[tm], ad);
            }
            const int brow = ks * 16 + (lane & 7) + (lane & 8);
            #pragma unroll
            for (int t2 = 0; t2 < 2; t2++) {
                int bq = wn * 4 + (lane >> 4) + t2 * 2;
                uint32_t bd = sbase + SB_H +
                              (uint32_t)(brow * 256 + ((bq ^ (lane & 7)) << 4));
                ldsm4t(bh[t2], bd);
            }
            #pragma unroll
            for (int tm = 0; tm < 4; tm++)
                #pragma unroll
                for (int tn = 0; tn < 4; tn++)
                    mma_f16(acc[tm][tn], ah[tm],
                            bh[tn >> 1][(tn & 1) * 2], bh[tn >> 1][(tn & 1) * 2 + 1]);
        }
    }

    #pragma unroll
    for (int tm = 0; tm < 4; tm++) {
        int r = row0 + wm * 64 + tm * 16 + (lane >> 2);
        #pragma unroll
        for (int tn = 0; tn < 4; tn++) {
            int c = col0 + wn * 32 + tn * 8 + 2 * (lane & 3);
            float2 bv = *(const float2*)(bias + c);
            float c0 = acc[tm][tn][0] + bv.x, c1 = acc[tm][tn][1] + bv.y;
            float c2 = acc[tm][tn][2] + bv.x, c3 = acc[tm][tn][3] + bv.y;
            if (Cf) {
                *(float2*)(Cf + (size_t)r * N + c) = make_float2(c0, c1);
                *(float2*)(Cf + (size_t)(r + 8) * N + c) = make_float2(c2, c3);
            } else {
                *(uint32_t*)(Hout + (size_t)r * N + c) = pack2h(c0, c1);
                *(uint32_t*)(Hout + (size_t)(r + 8) * N + c) = pack2h(c2, c3);
            }
        }
    }
}

// ---------------------------------------------------------------------------
// Attention, pure fp16, DOUBLE-BLOCK pipeline (R14 best-known config):
// each iteration loads 256 keys (two 128-key sub-blocks) into one 64KB
// buffer; 2 buffers, depth-1 prefetch. 8 warps = 4 row-groups x 2 key-halves.
// ---------------------------------------------------------------------------
#define AQ_H 0
#define AKV(buf) (16384 + (buf) * 65536)   // per buf: K 32K (256 rows), V 32K
#define A_RED 16384                        // 32KB reduction (reuses KV buf0 K)
#define A_SMEM 147456

__global__ __launch_bounds__(256, 1)
void attn_tc(const __half* __restrict__ kqv, __half* __restrict__ att)
{
    extern __shared__ char sm[];
    const uint32_t smb = smem_u32(sm);
    const int tid = threadIdx.x;
    const int w = tid >> 5, lane = tid & 31;
    const int wr = w >> 1;                  // row group 0..3 (32 rows each)
    const int wk = w & 1;                   // key half 0..1 (64 keys each)
    const int i = 31 - blockIdx.x;          // heavy tiles first
    const int h = blockIdx.y;
    const int row0 = i * 128;
    const int ldg = 3 * D_EMBD;
    const int lastrow = (i + 1) * 128;      // exclusive key-row bound

    const __half* qg = kqv + D_EMBD + h * D_HEAD;     // split order: k, q, v
    const __half* kg = kqv + h * D_HEAD;
    const __half* vg = kqv + 2 * D_EMBD + h * D_HEAD;

    #define KV_ISSUE_D(dblk, buf)                                               \
    do {                                                                        \
        uint32_t kb = smb + AKV(buf);                                           \
        int jr0 = (dblk) * 256;                                                 \
        _Pragma("unroll")                                                       \
        for (int l = 0; l < 8; l++) {                                           \
            int slot = tid + l * 256;                                           \
            int r = slot >> 3, q = slot & 7;                                    \
            if (jr0 + r < lastrow) {                                            \
                uint32_t d = (uint32_t)(r * 128 + ((q ^ (r & 7)) << 4));        \
                size_t go = (size_t)(jr0 + r) * ldg + q * 8;                    \
                cpa16(kb + d, kg + go);                                         \
                cpa16(kb + 32768 + d, vg + go);                                 \
            }                                                                   \
        }                                                                       \
    } while (0)

    const int nblocks = i + 1;
    const int ndbl = (nblocks + 1) >> 1;

    // issue group 0: Q tile + double-block 0
    #pragma unroll
    for (int l = 0; l < 2; l++) {
        int slot = tid + l * 256;
        int r = slot >> 2, q2 = (slot & 3) * 2;     // 2 chunks of 16B per row
        uint32_t d = (uint32_t)(r * 128 + ((q2 ^ (r & 7)) << 4));
        uint32_t d2 = (uint32_t)(r * 128 + (((q2 + 1) ^ (r & 7)) << 4));
        size_t go = (size_t)(row0 + r) * ldg + q2 * 8;
        cpa16(smb + AQ_H + d, qg + go);
        cpa16(smb + AQ_H + d2, qg + go + 8);
    }
    KV_ISSUE_D(0, 0);
    CP_COMMIT();
    CP_WAIT(0);
    __syncthreads();

    // ---- hoist Q fragments into registers (loop-invariant) ----
    uint32_t qf[4][2][4];
    #pragma unroll
    for (int ks = 0; ks < 4; ks++) {
        const int aq = ks * 2 + (lane >> 4);
        const uint32_t aswz = (uint32_t)((aq ^ (lane & 7)) << 4);
        #pragma unroll
        for (int rt = 0; rt < 2; rt++) {
            uint32_t ad = smb + AQ_H +
                          (uint32_t)((wr * 32 + rt * 16 + (lane & 15)) * 128) + aswz;
            ldsm4(qf[ks][rt], ad);
        }
    }

    float oacc[2][8][4];
    #pragma unroll
    for (int a = 0; a < 2; a++)
        #pragma unroll
        for (int b = 0; b < 8; b++)
            #pragma unroll
            for (int cc = 0; cc < 4; cc++) oacc[a][b][cc] = 0.0f;

    for (int dbl = 0; dbl < ndbl; dbl++) {
        if (dbl > 0) {
            CP_WAIT(0);
            __syncthreads();
        }
        if (dbl + 1 < ndbl) { KV_ISSUE_D(dbl + 1, (dbl + 1) & 1); CP_COMMIT(); }

        const uint32_t kvb = smb + AKV(dbl & 1);

        #pragma unroll
        for (int sub = 0; sub < 2; sub++) {
            const int b = 2 * dbl + sub;
            if (b >= nblocks) continue;
            const uint32_t kbase = kvb + (uint32_t)(sub * 16384);
            const uint32_t vbase = kvb + 32768 + (uint32_t)(sub * 16384);

            // ---- S = Q @ K^T ----
            float sacc[2][8][4];
            #pragma unroll
            for (int a = 0; a < 2; a++)
                #pragma unroll
                for (int bb = 0; bb < 8; bb++)
                    #pragma unroll
                    for (int cc = 0; cc < 4; cc++) sacc[a][bb][cc] = 0.0f;

            #pragma unroll
            for (int ks = 0; ks < 4; ks++) {
                uint32_t kb[4][4];
                const int kq = ks * 2 + ((lane >> 3) & 1);
                const uint32_t kswz = (uint32_t)((kq ^ (lane & 7)) << 4);
                #pragma unroll
                for (int g = 0; g < 4; g++) {
                    int krow = wk * 64 + g * 16 + (lane & 7) + ((lane >> 1) & 8);
                    ldsm4(kb[g], kbase + (uint32_t)(krow * 128) + kswz);
                }
                #pragma unroll
                for (int rt = 0; rt < 2; rt++)
                    #pragma unroll
                    for (int nt = 0; nt < 8; nt++)
                        mma_f16(sacc[rt][nt], qf[ks][rt],
                                kb[nt >> 1][(nt & 1) * 2], kb[nt >> 1][(nt & 1) * 2 + 1]);
            }

            // ---- causal mask (diag block only), in registers ----
            if (b == i) {
                #pragma unroll
                for (int rt = 0; rt < 2; rt++) {
                    int rl = wr * 32 + rt * 16 + (lane >> 2);
                    #pragma unroll
                    for (int nt = 0; nt < 8; nt++) {
                        int cl = wk * 64 + nt * 8 + 2 * (lane & 3);
                        if (cl     > rl)     sacc[rt][nt][0] = 0.0f;
                        if (cl + 1 > rl)     sacc[rt][nt][1] = 0.0f;
                        if (cl     > rl + 8) sacc[rt][nt][2] = 0.0f;
                        if (cl + 1 > rl + 8) sacc[rt][nt][3] = 0.0f;
                    }
                }
            }

            // ---- O += S @ V ----
            #pragma unroll
            for (int ksl = 0; ksl < 4; ksl++) {
                uint32_t sa[2][4], vb[4][4];
                #pragma unroll
                for (int rt = 0; rt < 2; rt++) {
                    sa[rt][0] = pack2h(sacc[rt][2 * ksl][0],     sacc[rt][2 * ksl][1]);
                    sa[rt][1] = pack2h(sacc[rt][2 * ksl][2],     sacc[rt][2 * ksl][3]);
                    sa[rt][2] = pack2h(sacc[rt][2 * ksl + 1][0], sacc[rt][2 * ksl + 1][1]);
                    sa[rt][3] = pack2h(sacc[rt][2 * ksl + 1][2], sacc[rt][2 * ksl + 1][3]);
                }
                const int vrow = wk * 64 + ksl * 16 + (lane & 7) + (lane & 8);
                #pragma unroll
                for (int g2 = 0; g2 < 4; g2++) {
                    int vq = g2 * 2 + (lane >> 4);
                    ldsm4t(vb[g2], vbase +
                           (uint32_t)(vrow * 128 + ((vq ^ (lane & 7)) << 4)));
                }
                #pragma unroll
                for (int rt = 0; rt < 2; rt++)
                    #pragma unroll
                    for (int nt = 0; nt < 8; nt++)
                        mma_f16(oacc[rt][nt], sa[rt],
                                vb[nt >> 1][(nt & 1) * 2], vb[nt >> 1][(nt & 1) * 2 + 1]);
            }
        }
    }

    // ---- cross-warp k-reduction (wk=1 -> smem, wk=0 adds) + epilogue ----
    __syncthreads();
    if (wk == 1) {
        #pragma unroll
        for (int rt = 0; rt < 2; rt++) {
            int r = wr * 32 + rt * 16 + (lane >> 2);
            #pragma unroll
            for (int nt = 0; nt < 8; nt++) {
                int c = nt * 8 + 2 * (lane & 3);
                *(float2*)(sm + A_RED + (size_t)(r * 64 + c) * 4) =
                    make_float2(oacc[rt][nt][0], oacc[rt][nt][1]);
                *(float2*)(sm + A_RED + (size_t)((r + 8) * 64 + c) * 4) =
                    make_float2(oacc[rt][nt][2], oacc[rt][nt][3]);
            }
        }
    }
    __syncthreads();
    if (wk == 0) {
        #pragma unroll
        for (int rt = 0; rt < 2; rt++) {
            int rl = wr * 32 + rt * 16 + (lane >> 2);
            int r = row0 + rl;
            #pragma unroll
            for (int nt = 0; nt < 8; nt++) {
                int cl = nt * 8 + 2 * (lane & 3);
                int c = h * D_HEAD + cl;
                float2 p0 = *(const float2*)(sm + A_RED + (size_t)(rl * 64 + cl) * 4);
                float2 p1 = *(const float2*)(sm + A_RED + (size_t)((rl + 8) * 64 + cl) * 4);
                *(uint32_t*)(att + (size_t)r * D_EMBD + c) =
                    pack2h(oacc[rt][nt][0] + p0.x, oacc[rt][nt][1] + p0.y);
                *(uint32_t*)(att + (size_t)(r + 8) * D_EMBD + c) =
                    pack2h(oacc[rt][nt][2] + p1.x, oacc[rt][nt][3] + p1.y);
            }
        }
    }
}

// ---------------------------------------------------------------------------
extern "C" void kernel_launch(void* const* d_in, const int* in_sizes, int n_in,
                              void* d_out, int out_size)
{
    const float* x  = (const float*)d_in[0];
    const float* W1 = (const float*)d_in[1];
    const float* b1 = (const float*)d_in[2];
    const float* W2 = (const float*)d_in[3];
    const float* b2 = (const float*)d_in[4];
    float* out = (float*)d_out;

    __half *xh, *w1h, *w2h, *kqv, *att;
    cudaGetSymbolAddress((void**)&xh, g_xh);
    cudaGetSymbolAddress((void**)&w1h, g_w1h);
    cudaGetSymbolAddress((void**)&w2h, g_w2h);
    cudaGetSymbolAddress((void**)&kqv, g_kqv);
    cudaGetSymbolAddress((void**)&att, g_att);

    cudaFuncSetAttribute(gemm_tc, cudaFuncAttributeMaxDynamicSharedMemorySize, G_SMEM);
    cudaFuncSetAttribute(attn_tc, cudaFuncAttributeMaxDynamicSharedMemorySize, A_SMEM);

    int nx = T_SEQ * D_EMBD, nw1 = D_EMBD * 3 * D_EMBD, nw2 = D_EMBD * D_EMBD;
    int total16 = (nx + nw1 + nw2) / 16;                 // threads (16 elems each)
    conv_all<<<(total16 + 255) / 256, 256>>>(x, xh, nx, W1, w1h, nw1, W2, w2h, nw2);

    // kqv = x @ W1 + b1   (fp16 output)
    gemm_tc<<<dim3(3 * D_EMBD / 128, T_SEQ / 128), 256, G_SMEM>>>(
        xh, w1h, b1, nullptr, kqv, T_SEQ, 3 * D_EMBD, D_EMBD);

    attn_tc<<<dim3(T_SEQ / 128, N_HEADS), 256, A_SMEM>>>(kqv, att);

    // out = att @ W2 + b2  (fp32 output)
    gemm_tc<<<dim3(D_EMBD / 128, T_SEQ / 128), 256, G_SMEM>>>(
        att, w2h, b2, out, nullptr, T_SEQ, D_EMBD, D_EMBD);
}